// round 2
// baseline (speedup 1.0000x reference)
#include <cuda_runtime.h>
#include <math.h>

// Problem constants
#define Bsz   4
#define Sq    2048
#define Dm    512
#define Hh    8
#define DEPTH 64
#define BAND  16
#define MTOT  (Bsz * Sq)   // 8192

// Scratch (device globals: allocation-guard safe)
__device__ float g_qh[Bsz * Sq * Dm];
__device__ float g_kh[Bsz * Sq * Dm];
__device__ float g_vh[Bsz * Sq * Dm];
__device__ float g_att[Bsz * Sq * Dm];

// ---------------------------------------------------------------------------
// SGEMM: Y[M x 512] = X[M x 512] @ W[512 x 512] + bias, fp32.
// 128x128 block tile, BK=8, 256 threads, 8x8 per-thread tile.
// ---------------------------------------------------------------------------
#define BM 128
#define BN 128
#define BK 8
#define TM 8
#define TN 8

__device__ __forceinline__ void sgemm_tile(const float* __restrict__ X,
                                           const float* __restrict__ W,
                                           const float* __restrict__ bias,
                                           float* __restrict__ Y) {
    __shared__ float As[BK][BM + 4];   // transposed A tile, padded (conflict-free)
    __shared__ float Bs[BK][BN];

    const int tid  = threadIdx.x;          // 0..255
    const int brow = blockIdx.x;           // M tile
    const int bcol = blockIdx.y;           // N tile
    const int tcol = tid & 15;             // 0..15
    const int trow = tid >> 4;             // 0..15

    float acc[TM][TN];
#pragma unroll
    for (int i = 0; i < TM; i++)
#pragma unroll
        for (int j = 0; j < TN; j++) acc[i][j] = 0.0f;

    // A tile load: 128 rows x 8 K, as 256 float4 (2 per row)
    const int aRow = tid >> 1;             // 0..127
    const int aCol = (tid & 1) * 4;        // 0 or 4
    // B tile load: 8 K-rows x 128 cols, as 256 float4 (32 per row)
    const int bRow = tid >> 5;             // 0..7
    const int bCol = (tid & 31) * 4;       // 0..124

    const float* Ap = X + (size_t)(brow * BM + aRow) * Dm + aCol;
    const float* Bp = W + (size_t)bRow * Dm + bcol * BN + bCol;

    for (int k0 = 0; k0 < Dm; k0 += BK) {
        float4 a4 = *(const float4*)(Ap + k0);
        float4 b4 = *(const float4*)(Bp + (size_t)k0 * Dm);

        As[aCol + 0][aRow] = a4.x;
        As[aCol + 1][aRow] = a4.y;
        As[aCol + 2][aRow] = a4.z;
        As[aCol + 3][aRow] = a4.w;
        *(float4*)&Bs[bRow][bCol] = b4;
        __syncthreads();

#pragma unroll
        for (int kk = 0; kk < BK; kk++) {
            float ar[TM], br[TN];
#pragma unroll
            for (int i = 0; i < TM; i++) ar[i] = As[kk][trow * TM + i];
#pragma unroll
            for (int j = 0; j < TN; j++) br[j] = Bs[kk][tcol * TN + j];
#pragma unroll
            for (int i = 0; i < TM; i++)
#pragma unroll
                for (int j = 0; j < TN; j++) acc[i][j] += ar[i] * br[j];
        }
        __syncthreads();
    }

    // Epilogue: add bias, store
    const int colBase = bcol * BN + tcol * TN;
#pragma unroll
    for (int i = 0; i < TM; i++) {
        const int row = brow * BM + trow * TM + i;
        float* yp = Y + (size_t)row * Dm + colBase;
#pragma unroll
        for (int j = 0; j < TN; j++) yp[j] = acc[i][j] + bias[colBase + j];
    }
}

// Fused QKV projection: z-dim selects (input, weight, bias, dest)
__global__ __launch_bounds__(256, 2) void qkv_proj_kernel(
    const float* __restrict__ q, const float* __restrict__ k, const float* __restrict__ v,
    const float* __restrict__ wq, const float* __restrict__ bq,
    const float* __restrict__ wk, const float* __restrict__ bk,
    const float* __restrict__ wv, const float* __restrict__ bv) {
    const float *X, *W, *bias;
    float* Y;
    if (blockIdx.z == 0)      { X = q; W = wq; bias = bq; Y = g_qh; }
    else if (blockIdx.z == 1) { X = k; W = wk; bias = bk; Y = g_kh; }
    else                      { X = v; W = wv; bias = bv; Y = g_vh; }
    sgemm_tile(X, W, bias, Y);
}

__global__ __launch_bounds__(256, 2) void out_proj_kernel(
    const float* __restrict__ wo, const float* __restrict__ bo,
    float* __restrict__ out) {
    sgemm_tile(g_att, wo, bo, out);
}

// ---------------------------------------------------------------------------
// Banded attention: window |q - k| <= BAND, per (b, h). Online softmax.
// Block: 32 queries x 8 threads = 256. Each thread owns an 8-float depth slice.
// ---------------------------------------------------------------------------
#define QB 32
#define KW (QB + 2 * BAND)   // 64-key window
#define KST 66               // smem row stride (conflict-free for this pattern)

__global__ __launch_bounds__(256, 4) void band_attn_kernel() {
    __shared__ float Ks[KW][KST];
    __shared__ float Vs[KW][KST];

    const int tid = threadIdx.x;
    const int q0  = blockIdx.x * QB;
    const int h   = blockIdx.y;
    const int b   = blockIdx.z;
    const size_t base = (size_t)b * Sq * Dm + (size_t)h * DEPTH;

    // Cooperative window load: 64 keys x 64 depth = 1024 float4
#pragma unroll
    for (int u = 0; u < 4; u++) {
        const int idx = tid + u * 256;
        const int r   = idx >> 4;          // key row 0..63
        const int c   = (idx & 15) * 4;    // depth col
        const int key = q0 - BAND + r;
        float4 k4 = make_float4(0.f, 0.f, 0.f, 0.f);
        float4 v4 = make_float4(0.f, 0.f, 0.f, 0.f);
        if (key >= 0 && key < Sq) {
            k4 = *(const float4*)(g_kh + base + (size_t)key * Dm + c);
            v4 = *(const float4*)(g_vh + base + (size_t)key * Dm + c);
        }
        Ks[r][c] = k4.x; Ks[r][c + 1] = k4.y; Ks[r][c + 2] = k4.z; Ks[r][c + 3] = k4.w;
        Vs[r][c] = v4.x; Vs[r][c + 1] = v4.y; Vs[r][c + 2] = v4.z; Vs[r][c + 3] = v4.w;
    }
    __syncthreads();

    const int qi = tid >> 3;            // query within block: 0..31
    const int ds = (tid & 7) * 8;       // this thread's depth slice
    const int gq = q0 + qi;

    float qr[8];
    const float* qp = g_qh + base + (size_t)gq * Dm + ds;
#pragma unroll
    for (int t = 0; t < 8; t++) qr[t] = qp[t];

    const float scale = 0.125f;         // 1/sqrt(64)
    float m = -1e30f, l = 0.0f;
    float accv[8];
#pragma unroll
    for (int t = 0; t < 8; t++) accv[t] = 0.0f;

#pragma unroll
    for (int w = -BAND; w <= BAND; w++) {
        const int j = gq + w;
        if ((unsigned)j >= (unsigned)Sq) continue;
        const int sj = qi + BAND + w;   // row in smem window

        float p = 0.0f;
#pragma unroll
        for (int t = 0; t < 8; t++) p += qr[t] * Ks[sj][ds + t];
        // reduce across the 8 threads that share this query
        p += __shfl_xor_sync(0xffffffffu, p, 1);
        p += __shfl_xor_sync(0xffffffffu, p, 2);
        p += __shfl_xor_sync(0xffffffffu, p, 4);

        const float logit = p * scale;
        const float mn = fmaxf(m, logit);
        const float co = __expf(m - mn);
        const float cp = __expf(logit - mn);
        l = l * co + cp;
#pragma unroll
        for (int t = 0; t < 8; t++) accv[t] = accv[t] * co + cp * Vs[sj][ds + t];
        m = mn;
    }

    const float inv = 1.0f / l;
    float* op = g_att + base + (size_t)gq * Dm + ds;
#pragma unroll
    for (int t = 0; t < 8; t++) op[t] = accv[t] * inv;
}

// ---------------------------------------------------------------------------
extern "C" void kernel_launch(void* const* d_in, const int* in_sizes, int n_in,
                              void* d_out, int out_size) {
    const float* q  = (const float*)d_in[0];
    const float* k  = (const float*)d_in[1];
    const float* v  = (const float*)d_in[2];
    const float* wq = (const float*)d_in[3];
    const float* bq = (const float*)d_in[4];
    const float* wk = (const float*)d_in[5];
    const float* bk = (const float*)d_in[6];
    const float* wv = (const float*)d_in[7];
    const float* bv = (const float*)d_in[8];
    const float* wo = (const float*)d_in[9];
    const float* bo = (const float*)d_in[10];
    float* out = (float*)d_out;

    dim3 gridQKV(MTOT / BM, Dm / BN, 3);      // 64 x 4 x 3
    qkv_proj_kernel<<<gridQKV, 256>>>(q, k, v, wq, bq, wk, bk, wv, bv);

    dim3 gridAtt(Sq / QB, Hh, Bsz);           // 64 x 8 x 4
    band_attn_kernel<<<gridAtt, 256>>>();

    dim3 gridOut(MTOT / BM, Dm / BN, 1);      // 64 x 4
    out_proj_kernel<<<gridOut, 256>>>(wo, bo, out);
}

// round 5
// speedup vs baseline: 2.1959x; 2.1959x over previous
#include <cuda_runtime.h>
#include <math.h>
#include <stdint.h>

// Problem constants
#define Bsz   4
#define Sq    2048
#define Dm    512
#define Hh    8
#define DEPTH 64
#define BAND  16
#define MTOT  (Bsz * Sq)   // 8192

// Scratch (device globals: allocation-guard safe)
__device__ float g_qh[Bsz * Sq * Dm];
__device__ float g_kh[Bsz * Sq * Dm];
__device__ float g_vh[Bsz * Sq * Dm];
__device__ float g_att[Bsz * Sq * Dm];

// ---------------------------------------------------------------------------
// TF32 tensor-core GEMM: Y[M x 512] = X[M x 512] @ W[512 x 512] + bias.
// Block tile 128x128, BK=16, 256 threads = 8 warps (2x4), warp tile 64x32.
// mma.sync.aligned.m16n8k8.row.col.f32.tf32.tf32.f32
// Double-buffered smem, register prefetch, 1 syncthreads per K-iter.
// ---------------------------------------------------------------------------
#define BM 128
#define BN 128
#define BK 16
#define APAD 20    // As row stride (words):  banks (20*r + c) % 32 all-distinct
#define BPAD 132   // Bs row stride (words):  banks (4*k + n) % 32 all-distinct

__device__ __forceinline__ uint32_t f2tf32(float x) {
    uint32_t r;
    asm("cvt.rna.tf32.f32 %0, %1;" : "=r"(r) : "f"(x));
    return r;
}

__device__ __forceinline__ void mma_tf32(float c[4], const uint32_t a[4], const uint32_t b[2]) {
    asm volatile(
        "mma.sync.aligned.m16n8k8.row.col.f32.tf32.tf32.f32 "
        "{%0,%1,%2,%3}, {%4,%5,%6,%7}, {%8,%9}, {%0,%1,%2,%3};"
        : "+f"(c[0]), "+f"(c[1]), "+f"(c[2]), "+f"(c[3])
        : "r"(a[0]), "r"(a[1]), "r"(a[2]), "r"(a[3]), "r"(b[0]), "r"(b[1]));
}

__device__ __forceinline__ void gemm_tf32_tile(const float* __restrict__ X,
                                               const float* __restrict__ W,
                                               const float* __restrict__ bias,
                                               float* __restrict__ Y) {
    __shared__ uint32_t As[2][BM][APAD];   // [buf][m][k] (tf32 bits)
    __shared__ uint32_t Bs[2][BK][BPAD];   // [buf][k][n] (tf32 bits)

    const int tid    = threadIdx.x;        // 0..255
    const int warp   = tid >> 5;           // 0..7
    const int lane   = tid & 31;
    const int wm     = warp >> 2;          // 0..1  (64-row slab)
    const int wn     = warp & 3;           // 0..3  (32-col slab)
    const int r      = lane >> 2;          // 0..7
    const int c      = lane & 3;           // 0..3

    const int rowBase = blockIdx.x * BM;
    const int colBase = blockIdx.y * BN;

    float acc[4][4][4];                    // [mi][ni][reg]
#pragma unroll
    for (int mi = 0; mi < 4; mi++)
#pragma unroll
        for (int ni = 0; ni < 4; ni++)
#pragma unroll
            for (int t = 0; t < 4; t++) acc[mi][ni][t] = 0.0f;

    // Global-load assignments (per thread: 2 float4 for A, 2 for B)
    const int aM0 = tid >> 2;              // u=0
    const int aK4 = (tid & 3) * 4;
    const int aM1 = (256 + tid) >> 2;      // u=1 (= aM0 + 64)
    const int bK0 = tid >> 5;
    const int bN4 = (tid & 31) * 4;
    const int bK1 = bK0 + 8;

    const float* Arow0 = X + (size_t)(rowBase + aM0) * Dm + aK4;
    const float* Arow1 = X + (size_t)(rowBase + aM1) * Dm + aK4;
    const float* Brow0 = W + (size_t)bK0 * Dm + colBase + bN4;
    const float* Brow1 = W + (size_t)bK1 * Dm + colBase + bN4;

    // Prologue: load tile 0 into buffer 0
    float4 a0 = *(const float4*)(Arow0);
    float4 a1 = *(const float4*)(Arow1);
    float4 b0 = *(const float4*)(Brow0);
    float4 b1 = *(const float4*)(Brow1);
    {
        uint32_t* p0 = &As[0][aM0][aK4];
        p0[0]=f2tf32(a0.x); p0[1]=f2tf32(a0.y); p0[2]=f2tf32(a0.z); p0[3]=f2tf32(a0.w);
        uint32_t* p1 = &As[0][aM1][aK4];
        p1[0]=f2tf32(a1.x); p1[1]=f2tf32(a1.y); p1[2]=f2tf32(a1.z); p1[3]=f2tf32(a1.w);
        uint32_t* q0 = &Bs[0][bK0][bN4];
        q0[0]=f2tf32(b0.x); q0[1]=f2tf32(b0.y); q0[2]=f2tf32(b0.z); q0[3]=f2tf32(b0.w);
        uint32_t* q1 = &Bs[0][bK1][bN4];
        q1[0]=f2tf32(b1.x); q1[1]=f2tf32(b1.y); q1[2]=f2tf32(b1.z); q1[3]=f2tf32(b1.w);
    }
    __syncthreads();

    const int NITER = Dm / BK;             // 32
    for (int it = 0; it < NITER; it++) {
        const int buf = it & 1;

        // Prefetch next tile into registers
        if (it + 1 < NITER) {
            const int koff = (it + 1) * BK;
            a0 = *(const float4*)(Arow0 + koff);
            a1 = *(const float4*)(Arow1 + koff);
            b0 = *(const float4*)(Brow0 + (size_t)koff * Dm);
            b1 = *(const float4*)(Brow1 + (size_t)koff * Dm);
        }

        // Compute on current buffer: 2 k8-steps
#pragma unroll
        for (int s = 0; s < 2; s++) {
            const int k8 = s * 8;
            uint32_t afr[4][4];
#pragma unroll
            for (int mi = 0; mi < 4; mi++) {
                const int m = wm * 64 + mi * 16 + r;
                afr[mi][0] = As[buf][m][k8 + c];
                afr[mi][1] = As[buf][m + 8][k8 + c];
                afr[mi][2] = As[buf][m][k8 + c + 4];
                afr[mi][3] = As[buf][m + 8][k8 + c + 4];
            }
            uint32_t bfr[4][2];
#pragma unroll
            for (int ni = 0; ni < 4; ni++) {
                const int n = wn * 32 + ni * 8 + r;
                bfr[ni][0] = Bs[buf][k8 + c][n];
                bfr[ni][1] = Bs[buf][k8 + c + 4][n];
            }
#pragma unroll
            for (int mi = 0; mi < 4; mi++)
#pragma unroll
                for (int ni = 0; ni < 4; ni++)
                    mma_tf32(acc[mi][ni], afr[mi], bfr[ni]);
        }

        // Stage next tile into the other buffer
        if (it + 1 < NITER) {
            const int nb = (it + 1) & 1;
            uint32_t* p0 = &As[nb][aM0][aK4];
            p0[0]=f2tf32(a0.x); p0[1]=f2tf32(a0.y); p0[2]=f2tf32(a0.z); p0[3]=f2tf32(a0.w);
            uint32_t* p1 = &As[nb][aM1][aK4];
            p1[0]=f2tf32(a1.x); p1[1]=f2tf32(a1.y); p1[2]=f2tf32(a1.z); p1[3]=f2tf32(a1.w);
            uint32_t* q0 = &Bs[nb][bK0][bN4];
            q0[0]=f2tf32(b0.x); q0[1]=f2tf32(b0.y); q0[2]=f2tf32(b0.z); q0[3]=f2tf32(b0.w);
            uint32_t* q1 = &Bs[nb][bK1][bN4];
            q1[0]=f2tf32(b1.x); q1[1]=f2tf32(b1.y); q1[2]=f2tf32(b1.z); q1[3]=f2tf32(b1.w);
        }
        __syncthreads();
    }

    // Epilogue: bias + store (float2 per (mi, ni, half))
#pragma unroll
    for (int mi = 0; mi < 4; mi++) {
        const int row0 = rowBase + wm * 64 + mi * 16 + r;
#pragma unroll
        for (int ni = 0; ni < 4; ni++) {
            const int col = colBase + wn * 32 + ni * 8 + c * 2;
            const float2 bv = *(const float2*)(bias + col);
            float2 v0 = make_float2(acc[mi][ni][0] + bv.x, acc[mi][ni][1] + bv.y);
            float2 v1 = make_float2(acc[mi][ni][2] + bv.x, acc[mi][ni][3] + bv.y);
            *(float2*)(Y + (size_t)row0 * Dm + col) = v0;
            *(float2*)(Y + (size_t)(row0 + 8) * Dm + col) = v1;
        }
    }
}

// Fused QKV projection: z-dim selects (input, weight, bias, dest)
__global__ __launch_bounds__(256, 2) void qkv_proj_kernel(
    const float* __restrict__ q, const float* __restrict__ k, const float* __restrict__ v,
    const float* __restrict__ wq, const float* __restrict__ bq,
    const float* __restrict__ wk, const float* __restrict__ bk,
    const float* __restrict__ wv, const float* __restrict__ bv) {
    const float *X, *W, *bias;
    float* Y;
    if (blockIdx.z == 0)      { X = q; W = wq; bias = bq; Y = g_qh; }
    else if (blockIdx.z == 1) { X = k; W = wk; bias = bk; Y = g_kh; }
    else                      { X = v; W = wv; bias = bv; Y = g_vh; }
    gemm_tf32_tile(X, W, bias, Y);
}

__global__ __launch_bounds__(256, 2) void out_proj_kernel(
    const float* __restrict__ wo, const float* __restrict__ bo,
    float* __restrict__ out) {
    gemm_tf32_tile(g_att, wo, bo, out);
}

// ---------------------------------------------------------------------------
// Banded attention: window |q - k| <= BAND, per (b, h). Online softmax.
// Block: 32 queries x 8 threads = 256. Each thread owns an 8-float depth slice.
// ---------------------------------------------------------------------------
#define QB 32
#define KW (QB + 2 * BAND)   // 64-key window
#define KST 66               // smem row stride (conflict-free for this pattern)

__global__ __launch_bounds__(256, 4) void band_attn_kernel() {
    __shared__ float Ks[KW][KST];
    __shared__ float Vs[KW][KST];

    const int tid = threadIdx.x;
    const int q0  = blockIdx.x * QB;
    const int h   = blockIdx.y;
    const int b   = blockIdx.z;
    const size_t base = (size_t)b * Sq * Dm + (size_t)h * DEPTH;

    // Cooperative window load: 64 keys x 64 depth = 1024 float4
#pragma unroll
    for (int u = 0; u < 4; u++) {
        const int idx = tid + u * 256;
        const int row = idx >> 4;          // key row 0..63
        const int col = (idx & 15) * 4;    // depth col
        const int key = q0 - BAND + row;
        float4 k4 = make_float4(0.f, 0.f, 0.f, 0.f);
        float4 v4 = make_float4(0.f, 0.f, 0.f, 0.f);
        if (key >= 0 && key < Sq) {
            k4 = *(const float4*)(g_kh + base + (size_t)key * Dm + col);
            v4 = *(const float4*)(g_vh + base + (size_t)key * Dm + col);
        }
        Ks[row][col] = k4.x; Ks[row][col + 1] = k4.y; Ks[row][col + 2] = k4.z; Ks[row][col + 3] = k4.w;
        Vs[row][col] = v4.x; Vs[row][col + 1] = v4.y; Vs[row][col + 2] = v4.z; Vs[row][col + 3] = v4.w;
    }
    __syncthreads();

    const int qi = tid >> 3;            // query within block: 0..31
    const int ds = (tid & 7) * 8;       // this thread's depth slice
    const int gq = q0 + qi;

    float qr[8];
    const float* qp = g_qh + base + (size_t)gq * Dm + ds;
#pragma unroll
    for (int t = 0; t < 8; t++) qr[t] = qp[t];

    const float scale = 0.125f;         // 1/sqrt(64)
    float m = -1e30f, l = 0.0f;
    float accv[8];
#pragma unroll
    for (int t = 0; t < 8; t++) accv[t] = 0.0f;

#pragma unroll
    for (int w = -BAND; w <= BAND; w++) {
        const int j = gq + w;
        if ((unsigned)j >= (unsigned)Sq) continue;
        const int sj = qi + BAND + w;   // row in smem window

        float p = 0.0f;
#pragma unroll
        for (int t = 0; t < 8; t++) p += qr[t] * Ks[sj][ds + t];
        // reduce across the 8 threads that share this query
        p += __shfl_xor_sync(0xffffffffu, p, 1);
        p += __shfl_xor_sync(0xffffffffu, p, 2);
        p += __shfl_xor_sync(0xffffffffu, p, 4);

        const float logit = p * scale;
        const float mn = fmaxf(m, logit);
        const float co = __expf(m - mn);
        const float cp = __expf(logit - mn);
        l = l * co + cp;
#pragma unroll
        for (int t = 0; t < 8; t++) accv[t] = accv[t] * co + cp * Vs[sj][ds + t];
        m = mn;
    }

    const float inv = 1.0f / l;
    float* op = g_att + base + (size_t)gq * Dm + ds;
#pragma unroll
    for (int t = 0; t < 8; t++) op[t] = accv[t] * inv;
}

// ---------------------------------------------------------------------------
extern "C" void kernel_launch(void* const* d_in, const int* in_sizes, int n_in,
                              void* d_out, int out_size) {
    const float* q  = (const float*)d_in[0];
    const float* k  = (const float*)d_in[1];
    const float* v  = (const float*)d_in[2];
    const float* wq = (const float*)d_in[3];
    const float* bq = (const float*)d_in[4];
    const float* wk = (const float*)d_in[5];
    const float* bk = (const float*)d_in[6];
    const float* wv = (const float*)d_in[7];
    const float* bv = (const float*)d_in[8];
    const float* wo = (const float*)d_in[9];
    const float* bo = (const float*)d_in[10];
    float* out = (float*)d_out;

    dim3 gridQKV(MTOT / BM, Dm / BN, 3);      // 64 x 4 x 3
    qkv_proj_kernel<<<gridQKV, 256>>>(q, k, v, wq, bq, wk, bk, wv, bv);

    dim3 gridAtt(Sq / QB, Hh, Bsz);           // 64 x 8 x 4
    band_attn_kernel<<<gridAtt, 256>>>();

    dim3 gridOut(MTOT / BM, Dm / BN, 1);      // 64 x 4
    out_proj_kernel<<<gridOut, 256>>>(wo, bo, out);
}